// round 12
// baseline (speedup 1.0000x reference)
#include <cuda_runtime.h>
#include <cstdint>

#define TT 512
#define DD 256
#define LL 256
#define HH 512
#define ZDIM 1024
#define CLU 16   // CTAs per cluster = per LSTM direction (nonportable size)

// ---------------- device scratch (no allocations allowed) ----------------
__device__ __align__(16) float g_xw_a[TT * ZDIM];
__device__ __align__(16) float g_xw_b[TT * ZDIM];
__device__ __align__(16) float g_Ut[4][ZDIM * LL];   // transposed U: [col = gate*256+u][k]
__device__ __align__(16) float g_v[TT * 2 * LL];     // layer-1 bilstm output (concat layout)
__device__ __align__(16) float g_hcat[TT * 2 * LL];  // layer-2 bilstm output (concat layout)
__device__ __align__(16) float g_headf[TT * HH];
__device__ __align__(16) float g_modf[TT * HH];

// ---------------- fast activations ----------------
__device__ __forceinline__ float fsig(float x) {     // rel err ~1e-6 (exp-based; used in LSTM)
    float e = __expf(-x);
    return __fdividef(1.f, 1.f + e);
}
__device__ __forceinline__ float ftanh(float x) {    // rel err ~1e-6 (exp-based; used in LSTM)
    float e = __expf(2.f * x);
    return 1.f - __fdividef(2.f, e + 1.f);
}
__device__ __forceinline__ float ftanh_hw(float x) { // MUFU tanh (head only; errors average out)
    float r;
    asm("tanh.approx.f32 %0, %1;" : "=f"(r) : "f"(x));
    return r;
}

__device__ __forceinline__ uint32_t smem_u32(const void* p) {
    uint32_t a;
    asm("{ .reg .u64 t; cvta.to.shared.u64 t, %1; cvt.u32.u64 %0, t; }" : "=r"(a) : "l"(p));
    return a;
}

// try_wait parity with sleep (acquire)
__device__ __forceinline__ void mbar_wait_parity(uint32_t mbar, uint32_t parity) {
    uint32_t done;
    asm volatile(
        "{\n\t"
        ".reg .pred p;\n\t"
        "mbarrier.try_wait.parity.acquire.cta.shared::cta.b64 p, [%1], %2;\n\t"
        "selp.b32 %0, 1, 0, p;\n\t"
        "}"
        : "=r"(done) : "r"(mbar), "r"(parity) : "memory");
    if (!done) {
        asm volatile(
            "{\n\t"
            ".reg .pred P1;\n\t"
            "WAIT_LOOP_%=:\n\t"
            "mbarrier.try_wait.parity.acquire.cta.shared::cta.b64 P1, [%0], %1, 0x989680;\n\t"
            "@P1 bra.uni WAIT_DONE_%=;\n\t"
            "bra.uni WAIT_LOOP_%=;\n\t"
            "WAIT_DONE_%=:\n\t"
            "}"
            :: "r"(mbar), "r"(parity) : "memory");
    }
}

// ---------------- U transpose: [256,1024] -> [1024,256] x4 ----------------
__global__ void transposeU_kernel(const float* __restrict__ u0, const float* __restrict__ u1,
                                  const float* __restrict__ u2, const float* __restrict__ u3) {
    __shared__ float tile[32][33];
    const float* src = (blockIdx.z == 0) ? u0 : (blockIdx.z == 1) ? u1 : (blockIdx.z == 2) ? u2 : u3;
    float* dst = g_Ut[blockIdx.z];
    int j  = blockIdx.x * 32 + threadIdx.x;   // column in U (0..1023)
    int k0 = blockIdx.y * 32;                 // row chunk (0..255)
#pragma unroll
    for (int r = 0; r < 32; r += 8)
        tile[threadIdx.y + r][threadIdx.x] = src[(k0 + threadIdx.y + r) * ZDIM + j];
    __syncthreads();
    int k  = k0 + threadIdx.x;
    int jo = blockIdx.x * 32;
#pragma unroll
    for (int r = 0; r < 32; r += 8)
        dst[(jo + threadIdx.y + r) * LL + k] = tile[threadIdx.x][threadIdx.y + r];
}

// ---------------- dual fp32 tiled GEMM, double-buffered smem ----------------
__global__ void __launch_bounds__(256) gemm2_kernel(
    const float* __restrict__ A0, const float* __restrict__ A1,
    const float* __restrict__ B0, const float* __restrict__ B1,
    const float* __restrict__ bias0, const float* __restrict__ bias1,
    float* __restrict__ C0, float* __restrict__ C1,
    int M, int N, int K) {
    const float* A    = (blockIdx.z == 0) ? A0 : A1;
    const float* B    = (blockIdx.z == 0) ? B0 : B1;
    const float* bias = (blockIdx.z == 0) ? bias0 : bias1;
    float* C          = (blockIdx.z == 0) ? C0 : C1;

    __shared__ __align__(16) float As[2][16][68];
    __shared__ __align__(16) float Bs[2][16][68];
    const int tid = threadIdx.x;
    const int tx = tid & 15, ty = tid >> 4;
    const int bm = blockIdx.y * 64, bn = blockIdx.x * 64;

    const int ar = tid >> 2;            // A row 0..63
    const int ac = (tid & 3) * 4;       // A col 0,4,8,12
    const int br = tid >> 4;            // B row 0..15
    const int bc = (tid & 15) * 4;      // B col 0..60

    float acc[4][4];
#pragma unroll
    for (int i = 0; i < 4; i++)
#pragma unroll
        for (int j = 0; j < 4; j++) acc[i][j] = 0.f;

    // prologue: block 0 -> buffer 0
    {
        float4 av = *(const float4*)&A[(bm + ar) * K + ac];
        As[0][ac + 0][ar] = av.x; As[0][ac + 1][ar] = av.y;
        As[0][ac + 2][ar] = av.z; As[0][ac + 3][ar] = av.w;
        float4 bv = *(const float4*)&B[br * N + bn + bc];
        *(float4*)&Bs[0][br][bc] = bv;
    }
    __syncthreads();

    int p = 0;
    for (int k0 = 16; k0 < K; k0 += 16) {
        float4 av = *(const float4*)&A[(bm + ar) * K + k0 + ac];
        float4 bv = *(const float4*)&B[(k0 + br) * N + bn + bc];

        {
            const float (*Ac)[68] = As[p];
            const float (*Bc)[68] = Bs[p];
#pragma unroll
            for (int kk = 0; kk < 16; kk++) {
                float4 a4 = *(const float4*)&Ac[kk][ty * 4];
                float4 b4 = *(const float4*)&Bc[kk][tx * 4];
                acc[0][0] += a4.x * b4.x; acc[0][1] += a4.x * b4.y; acc[0][2] += a4.x * b4.z; acc[0][3] += a4.x * b4.w;
                acc[1][0] += a4.y * b4.x; acc[1][1] += a4.y * b4.y; acc[1][2] += a4.y * b4.z; acc[1][3] += a4.y * b4.w;
                acc[2][0] += a4.z * b4.x; acc[2][1] += a4.z * b4.y; acc[2][2] += a4.z * b4.z; acc[2][3] += a4.z * b4.w;
                acc[3][0] += a4.w * b4.x; acc[3][1] += a4.w * b4.y; acc[3][2] += a4.w * b4.z; acc[3][3] += a4.w * b4.w;
            }
        }

        p ^= 1;
        As[p][ac + 0][ar] = av.x; As[p][ac + 1][ar] = av.y;
        As[p][ac + 2][ar] = av.z; As[p][ac + 3][ar] = av.w;
        *(float4*)&Bs[p][br][bc] = bv;
        __syncthreads();
    }

    {
        const float (*Ac)[68] = As[p];
        const float (*Bc)[68] = Bs[p];
#pragma unroll
        for (int kk = 0; kk < 16; kk++) {
            float4 a4 = *(const float4*)&Ac[kk][ty * 4];
            float4 b4 = *(const float4*)&Bc[kk][tx * 4];
            acc[0][0] += a4.x * b4.x; acc[0][1] += a4.x * b4.y; acc[0][2] += a4.x * b4.z; acc[0][3] += a4.x * b4.w;
            acc[1][0] += a4.y * b4.x; acc[1][1] += a4.y * b4.y; acc[1][2] += a4.y * b4.z; acc[1][3] += a4.y * b4.w;
            acc[2][0] += a4.z * b4.x; acc[2][1] += a4.z * b4.y; acc[2][2] += a4.z * b4.z; acc[2][3] += a4.z * b4.w;
            acc[3][0] += a4.w * b4.x; acc[3][1] += a4.w * b4.y; acc[3][2] += a4.w * b4.z; acc[3][3] += a4.w * b4.w;
        }
    }

#pragma unroll
    for (int i = 0; i < 4; i++) {
        int row = bm + ty * 4 + i;
#pragma unroll
        for (int j = 0; j < 4; j++) {
            int col = bn + tx * 4 + j;
            float v = acc[i][j];
            if (bias) v += bias[col];
            C[row * N + col] = v;
        }
    }
}

// ---------------- cluster LSTM: one 16-CTA cluster per direction ----------------
// grid = 32 CTAs (2 clusters of 16). 256 threads/CTA. Each CTA owns 16 units;
// warp owns 2 units (up = lane>>4) x 16 k-slices (sl = lane&15) -> 64 FMA/thread
// -> 256-cyc SMSP issue floor. Butterfly reduce leaves gate sums in ALL 16
// lanes; all lanes redundantly run activations + carry c; each lane pushes its
// unit's h to exactly ONE CTA (rank sl) -> the whole 16-way broadcast is ONE
// st.async instruction per warp. No in-loop __syncthreads (R11-proven).
__global__ void __launch_bounds__(256, 1) __cluster_dims__(CLU, 1, 1)
lstm_cluster_kernel(int layer) {
    const int dir = blockIdx.x / CLU;     // 0 = forward, 1 = backward
    uint32_t rank;
    asm("mov.u32 %0, %%cluster_ctarank;" : "=r"(rank));

    const float* xw = (dir == 0) ? g_xw_a : g_xw_b;
    const float* Ut = g_Ut[layer * 2 + dir];
    float* out = (layer == 0) ? g_v : g_hcat;
    const int coloff = dir * LL;          // concat column offset

    const int tid  = threadIdx.x;
    const int warp = tid >> 5, lane = tid & 31;
    const int up = lane >> 4, sl = lane & 15;   // unit-in-warp, k-slice / target rank
    const int u = rank * 16 + warp * 2 + up;    // hidden unit owned

    __shared__ __align__(16) float h_s[2][LL];
    __shared__ __align__(8) unsigned long long mbar[2];

    // U slice in registers: 4 gates x 4 float4 = 64 regs. k = j*64 + sl*4.
    float4 Ug[4][4];
#pragma unroll
    for (int g = 0; g < 4; g++)
#pragma unroll
        for (int j = 0; j < 4; j++)
            Ug[g][j] = *(const float4*)&Ut[(g * LL + u) * LL + j * 64 + sl * 4];

    const uint32_t bar0 = smem_u32(&mbar[0]);
    const uint32_t bar1 = smem_u32(&mbar[1]);

    // init: zero h buffer 0, init barriers, post initial expects
    h_s[0][tid] = 0.f;
    if (tid == 0) {
        asm volatile("mbarrier.init.shared.b64 [%0], 1;" :: "r"(bar0) : "memory");
        asm volatile("mbarrier.init.shared.b64 [%0], 1;" :: "r"(bar1) : "memory");
        asm volatile("mbarrier.arrive.expect_tx.shared.b64 _, [%0], %1;" :: "r"(bar1), "r"(LL * 4) : "memory");
        asm volatile("mbarrier.arrive.expect_tx.shared.b64 _, [%0], %1;" :: "r"(bar0), "r"(LL * 4) : "memory");
    }
    __syncthreads();
    // barriers + zeroed h must be visible cluster-wide before any st.async lands
    asm volatile("barrier.cluster.arrive.aligned;" ::: "memory");
    asm volatile("barrier.cluster.wait.aligned;" ::: "memory");

    // per-lane DSMEM target: this lane pushes unit u's h to CTA rank sl.
    const uint32_t h0u = smem_u32(&h_s[0][u]);
    uint32_t dHme;
    asm("mapa.shared::cluster.u32 %0, %1, %2;" : "=r"(dHme) : "r"(h0u), "r"(sl));
    const uint32_t offB0 = bar0 - h0u;          // delta to mbar[0]
    const uint32_t offB1 = bar1 - h0u;          // delta to mbar[1]
    const uint32_t offH1 = (uint32_t)(LL * 4);  // delta h_s[1] - h_s[0]

    float c = 0.f;                              // carried redundantly in all 16 lanes
    uint32_t ph0 = 0, ph1 = 0;                  // phase parity per barrier

    // prefetch xw for the first token (all lanes: same address per unit group)
    const int tok0 = (dir == 0) ? 0 : (TT - 1);
    float xwv0, xwv1, xwv2, xwv3;
    {
        const float* xp = &xw[tok0 * ZDIM + u];
        xwv0 = __ldg(xp + 0 * LL);
        xwv1 = __ldg(xp + 1 * LL);
        xwv2 = __ldg(xp + 2 * LL);
        xwv3 = __ldg(xp + 3 * LL);
    }

    for (int s = 0; s < TT; s++) {
        if (s > 0) {
            const uint32_t b = (s & 1) ? bar1 : bar0;
            uint32_t& ph = (s & 1) ? ph1 : ph0;
            mbar_wait_parity(b, ph);
            ph ^= 1;
            // re-arm for this barrier's next use (step s+2). Early completes are
            // absorbed by signed mbarrier tx accounting (R11-proven).
            if (tid == 0)
                asm volatile("mbarrier.arrive.expect_tx.shared.b64 _, [%0], %1;" :: "r"(b), "r"(LL * 4) : "memory");
        }

        const float* hc = h_s[s & 1];
        const int tok = (dir == 0) ? s : (TT - 1 - s);

        // load h slice: k = j*64 + sl*4
        float4 h4[4];
#pragma unroll
        for (int j = 0; j < 4; j++)
            h4[j] = *(const float4*)&hc[j * 64 + sl * 4];

        float acc0 = 0.f, acc1 = 0.f, acc2 = 0.f, acc3 = 0.f;
#pragma unroll
        for (int j = 0; j < 4; j++) {
            float4 a;
            a = Ug[0][j]; acc0 += a.x * h4[j].x + a.y * h4[j].y + a.z * h4[j].z + a.w * h4[j].w;
            a = Ug[1][j]; acc1 += a.x * h4[j].x + a.y * h4[j].y + a.z * h4[j].z + a.w * h4[j].w;
            a = Ug[2][j]; acc2 += a.x * h4[j].x + a.y * h4[j].y + a.z * h4[j].z + a.w * h4[j].w;
            a = Ug[3][j]; acc3 += a.x * h4[j].x + a.y * h4[j].y + a.z * h4[j].z + a.w * h4[j].w;
        }
        // butterfly reduce across the 16 slices: result in ALL lanes
#pragma unroll
        for (int off = 8; off; off >>= 1) {
            acc0 += __shfl_xor_sync(0xffffffffu, acc0, off, 16);
            acc1 += __shfl_xor_sync(0xffffffffu, acc1, off, 16);
            acc2 += __shfl_xor_sync(0xffffffffu, acc2, off, 16);
            acc3 += __shfl_xor_sync(0xffffffffu, acc3, off, 16);
        }

        // all lanes compute the gates redundantly (bitwise-identical)
        float iv = fsig(acc0 + xwv0);
        float fv = fsig(acc1 + xwv1);
        float gv = ftanh(acc2 + xwv2);
        float ov = fsig(acc3 + xwv3);
        c = fv * c + iv * gv;
        float hv = ov * ftanh(c);

        if (s + 1 < TT) {
            // lane-parallel broadcast: ONE st.async per warp covers 2 units x 16 CTAs
            const uint32_t q = (s + 1) & 1;
            const uint32_t offH = q ? offH1 : 0u;
            const uint32_t offB = q ? offB1 : offB0;
            asm volatile(
                "st.async.shared::cluster.mbarrier::complete_tx::bytes.b32 [%0], %1, [%2];"
                :: "r"(dHme + offH), "r"(__float_as_uint(hv)), "r"(dHme + offB) : "memory");
        }

        if (sl == 0)
            out[tok * (2 * LL) + coloff + u] = hv;

        if (s + 1 < TT) {
            // prefetch next token's xw while the cluster syncs
            const int ntok = (dir == 0) ? (s + 1) : (TT - 2 - s);
            const float* xp = &xw[ntok * ZDIM + u];
            xwv0 = __ldg(xp + 0 * LL);
            xwv1 = __ldg(xp + 1 * LL);
            xwv2 = __ldg(xp + 2 * LL);
            xwv3 = __ldg(xp + 3 * LL);
        }
    }

    // hygiene: no CTA exits while peers could still address its SMEM
    asm volatile("barrier.cluster.arrive.aligned;" ::: "memory");
    asm volatile("barrier.cluster.wait.aligned;" ::: "memory");
}

// ---------------- pairwise head: out[i,j] = sum_h w[h]*tanh(hf[i,h]+mf[j,h]) + ob ----------------
__global__ void __launch_bounds__(256) pairwise_kernel(
    const float* __restrict__ headf, const float* __restrict__ modf,
    const float* __restrict__ outW, const float* __restrict__ outB,
    float* __restrict__ out) {
    __shared__ __align__(16) float SH[32][132];
    __shared__ float SMt[128][33];
    __shared__ __align__(16) float Wsh[128];

    const int t = threadIdx.x;
    const int i0 = blockIdx.y * 32, j0 = blockIdx.x * 32;
    const int li = t >> 3;
    const int lj = (t & 7) * 4;

    float acc0 = 0.f, acc1 = 0.f, acc2 = 0.f, acc3 = 0.f;

    for (int hc = 0; hc < HH; hc += 128) {
#pragma unroll
        for (int r = 0; r < 4; r++) {
            int idx = t + r * 256;
            int row = idx >> 5;
            int c4 = (idx & 31) * 4;
            float4 hvv = *(const float4*)&headf[(i0 + row) * HH + hc + c4];
            *(float4*)&SH[row][c4] = hvv;
            float4 mvv = *(const float4*)&modf[(j0 + row) * HH + hc + c4];
            SMt[c4 + 0][row] = mvv.x; SMt[c4 + 1][row] = mvv.y;
            SMt[c4 + 2][row] = mvv.z; SMt[c4 + 3][row] = mvv.w;
        }
        if (t < 32) *(float4*)&Wsh[t * 4] = *(const float4*)&outW[hc + t * 4];
        __syncthreads();

#pragma unroll 4
        for (int h = 0; h < 128; h++) {
            float hv = SH[li][h];
            float w = Wsh[h];
            acc0 += w * ftanh_hw(hv + SMt[h][lj + 0]);
            acc1 += w * ftanh_hw(hv + SMt[h][lj + 1]);
            acc2 += w * ftanh_hw(hv + SMt[h][lj + 2]);
            acc3 += w * ftanh_hw(hv + SMt[h][lj + 3]);
        }
        __syncthreads();
    }

    const float ob = outB[0];
    float* orow = &out[(i0 + li) * TT + j0 + lj];
    orow[0] = acc0 + ob;
    orow[1] = acc1 + ob;
    orow[2] = acc2 + ob;
    orow[3] = acc3 + ob;
}

// ---------------- host side ----------------
extern "C" void kernel_launch(void* const* d_in, const int* in_sizes, int n_in,
                              void* d_out, int out_size) {
    (void)in_sizes; (void)n_in; (void)out_size;
    const float* emb     = (const float*)d_in[0];
    const float* W_f1    = (const float*)d_in[1];
    const float* U_f1    = (const float*)d_in[2];
    const float* b_f1    = (const float*)d_in[3];
    const float* W_b1    = (const float*)d_in[4];
    const float* U_b1    = (const float*)d_in[5];
    const float* b_b1    = (const float*)d_in[6];
    const float* W_f2    = (const float*)d_in[7];
    const float* U_f2    = (const float*)d_in[8];
    const float* b_f2    = (const float*)d_in[9];
    const float* W_b2    = (const float*)d_in[10];
    const float* U_b2    = (const float*)d_in[11];
    const float* b_b2    = (const float*)d_in[12];
    const float* FOH     = (const float*)d_in[13];
    const float* FOM     = (const float*)d_in[14];
    const float* hidBias = (const float*)d_in[15];
    const float* outW    = (const float*)d_in[16];
    const float* outBias = (const float*)d_in[17];

    float *xwa, *xwb, *v, *hcat, *headf, *modf;
    cudaGetSymbolAddress((void**)&xwa,   g_xw_a);
    cudaGetSymbolAddress((void**)&xwb,   g_xw_b);
    cudaGetSymbolAddress((void**)&v,     g_v);
    cudaGetSymbolAddress((void**)&hcat,  g_hcat);
    cudaGetSymbolAddress((void**)&headf, g_headf);
    cudaGetSymbolAddress((void**)&modf,  g_modf);

    // allow 16-CTA (nonportable) clusters for the LSTM kernel (idempotent)
    cudaFuncSetAttribute(lstm_cluster_kernel,
                         cudaFuncAttributeNonPortableClusterSizeAllowed, 1);

    // 1. transpose all recurrent matrices
    transposeU_kernel<<<dim3(ZDIM / 32, LL / 32, 4), dim3(32, 8)>>>(U_f1, U_b1, U_f2, U_b2);

    // 2. layer-1 input projections (both directions, bias folded in)
    gemm2_kernel<<<dim3(ZDIM / 64, TT / 64, 2), 256>>>(
        emb, emb, W_f1, W_b1, b_f1, b_b1, xwa, xwb, TT, ZDIM, DD);

    // 3. layer-1 BiLSTM (fw + bw clusters concurrently), writes concat layout -> v
    lstm_cluster_kernel<<<2 * CLU, 256>>>(0);

    // 4. layer-2 input projections
    gemm2_kernel<<<dim3(ZDIM / 64, TT / 64, 2), 256>>>(
        v, v, W_f2, W_b2, b_f2, b_b2, xwa, xwb, TT, ZDIM, 2 * LL);

    // 5. layer-2 BiLSTM -> hcat
    lstm_cluster_kernel<<<2 * CLU, 256>>>(1);

    // 6. head projections (hidBias folded into headfov)
    gemm2_kernel<<<dim3(HH / 64, TT / 64, 2), 256>>>(
        hcat, hcat, FOH, FOM, hidBias, nullptr, headf, modf, TT, HH, 2 * LL);

    // 7. pairwise scores
    pairwise_kernel<<<dim3(TT / 32, TT / 32), 256>>>(headf, modf, outW, outBias, (float*)d_out);
}

// round 13
// speedup vs baseline: 1.2524x; 1.2524x over previous
#include <cuda_runtime.h>
#include <cstdint>

#define TT 512
#define DD 256
#define LL 256
#define HH 512
#define ZDIM 1024
#define CLU 8    // CTAs per cluster = per LSTM direction

// ---------------- device scratch (no allocations allowed) ----------------
__device__ __align__(16) float g_xw_a[TT * ZDIM];
__device__ __align__(16) float g_xw_b[TT * ZDIM];
__device__ __align__(16) float g_Ut[4][ZDIM * LL];   // transposed U: [col = gate*256+u][k]
__device__ __align__(16) float g_v[TT * 2 * LL];     // layer-1 bilstm output (concat layout)
__device__ __align__(16) float g_hcat[TT * 2 * LL];  // layer-2 bilstm output (concat layout)
__device__ __align__(16) float g_headf[TT * HH];
__device__ __align__(16) float g_modf[TT * HH];

// ---------------- fast activations ----------------
__device__ __forceinline__ float ftanh_hw(float x) { // MUFU tanh (abs err ~1.4e-4)
    float r;
    asm("tanh.approx.f32 %0, %1;" : "=f"(r) : "f"(x));
    return r;
}
__device__ __forceinline__ float fsig_hw(float x) {  // sigmoid via MUFU tanh
    return fmaf(ftanh_hw(0.5f * x), 0.5f, 0.5f);
}

__device__ __forceinline__ uint32_t smem_u32(const void* p) {
    uint32_t a;
    asm("{ .reg .u64 t; cvta.to.shared.u64 t, %1; cvt.u32.u64 %0, t; }" : "=r"(a) : "l"(p));
    return a;
}

// try_wait parity with sleep (acquire)
__device__ __forceinline__ void mbar_wait_parity(uint32_t mbar, uint32_t parity) {
    uint32_t done;
    asm volatile(
        "{\n\t"
        ".reg .pred p;\n\t"
        "mbarrier.try_wait.parity.acquire.cta.shared::cta.b64 p, [%1], %2;\n\t"
        "selp.b32 %0, 1, 0, p;\n\t"
        "}"
        : "=r"(done) : "r"(mbar), "r"(parity) : "memory");
    if (!done) {
        asm volatile(
            "{\n\t"
            ".reg .pred P1;\n\t"
            "WAIT_LOOP_%=:\n\t"
            "mbarrier.try_wait.parity.acquire.cta.shared::cta.b64 P1, [%0], %1, 0x989680;\n\t"
            "@P1 bra.uni WAIT_DONE_%=;\n\t"
            "bra.uni WAIT_LOOP_%=;\n\t"
            "WAIT_DONE_%=:\n\t"
            "}"
            :: "r"(mbar), "r"(parity) : "memory");
    }
}

// ---------------- U transpose: [256,1024] -> [1024,256] x4 ----------------
__global__ void transposeU_kernel(const float* __restrict__ u0, const float* __restrict__ u1,
                                  const float* __restrict__ u2, const float* __restrict__ u3) {
    __shared__ float tile[32][33];
    const float* src = (blockIdx.z == 0) ? u0 : (blockIdx.z == 1) ? u1 : (blockIdx.z == 2) ? u2 : u3;
    float* dst = g_Ut[blockIdx.z];
    int j  = blockIdx.x * 32 + threadIdx.x;   // column in U (0..1023)
    int k0 = blockIdx.y * 32;                 // row chunk (0..255)
#pragma unroll
    for (int r = 0; r < 32; r += 8)
        tile[threadIdx.y + r][threadIdx.x] = src[(k0 + threadIdx.y + r) * ZDIM + j];
    __syncthreads();
    int k  = k0 + threadIdx.x;
    int jo = blockIdx.x * 32;
#pragma unroll
    for (int r = 0; r < 32; r += 8)
        dst[(jo + threadIdx.y + r) * LL + k] = tile[threadIdx.x][threadIdx.y + r];
}

// ---------------- dual fp32 tiled GEMM, double-buffered smem ----------------
__global__ void __launch_bounds__(256) gemm2_kernel(
    const float* __restrict__ A0, const float* __restrict__ A1,
    const float* __restrict__ B0, const float* __restrict__ B1,
    const float* __restrict__ bias0, const float* __restrict__ bias1,
    float* __restrict__ C0, float* __restrict__ C1,
    int M, int N, int K) {
    const float* A    = (blockIdx.z == 0) ? A0 : A1;
    const float* B    = (blockIdx.z == 0) ? B0 : B1;
    const float* bias = (blockIdx.z == 0) ? bias0 : bias1;
    float* C          = (blockIdx.z == 0) ? C0 : C1;

    __shared__ __align__(16) float As[2][16][68];
    __shared__ __align__(16) float Bs[2][16][68];
    const int tid = threadIdx.x;
    const int tx = tid & 15, ty = tid >> 4;
    const int bm = blockIdx.y * 64, bn = blockIdx.x * 64;

    const int ar = tid >> 2;            // A row 0..63
    const int ac = (tid & 3) * 4;       // A col 0,4,8,12
    const int br = tid >> 4;            // B row 0..15
    const int bc = (tid & 15) * 4;      // B col 0..60

    float acc[4][4];
#pragma unroll
    for (int i = 0; i < 4; i++)
#pragma unroll
        for (int j = 0; j < 4; j++) acc[i][j] = 0.f;

    // prologue: block 0 -> buffer 0
    {
        float4 av = *(const float4*)&A[(bm + ar) * K + ac];
        As[0][ac + 0][ar] = av.x; As[0][ac + 1][ar] = av.y;
        As[0][ac + 2][ar] = av.z; As[0][ac + 3][ar] = av.w;
        float4 bv = *(const float4*)&B[br * N + bn + bc];
        *(float4*)&Bs[0][br][bc] = bv;
    }
    __syncthreads();

    int p = 0;
    for (int k0 = 16; k0 < K; k0 += 16) {
        float4 av = *(const float4*)&A[(bm + ar) * K + k0 + ac];
        float4 bv = *(const float4*)&B[(k0 + br) * N + bn + bc];

        {
            const float (*Ac)[68] = As[p];
            const float (*Bc)[68] = Bs[p];
#pragma unroll
            for (int kk = 0; kk < 16; kk++) {
                float4 a4 = *(const float4*)&Ac[kk][ty * 4];
                float4 b4 = *(const float4*)&Bc[kk][tx * 4];
                acc[0][0] += a4.x * b4.x; acc[0][1] += a4.x * b4.y; acc[0][2] += a4.x * b4.z; acc[0][3] += a4.x * b4.w;
                acc[1][0] += a4.y * b4.x; acc[1][1] += a4.y * b4.y; acc[1][2] += a4.y * b4.z; acc[1][3] += a4.y * b4.w;
                acc[2][0] += a4.z * b4.x; acc[2][1] += a4.z * b4.y; acc[2][2] += a4.z * b4.z; acc[2][3] += a4.z * b4.w;
                acc[3][0] += a4.w * b4.x; acc[3][1] += a4.w * b4.y; acc[3][2] += a4.w * b4.z; acc[3][3] += a4.w * b4.w;
            }
        }

        p ^= 1;
        As[p][ac + 0][ar] = av.x; As[p][ac + 1][ar] = av.y;
        As[p][ac + 2][ar] = av.z; As[p][ac + 3][ar] = av.w;
        *(float4*)&Bs[p][br][bc] = bv;
        __syncthreads();
    }

    {
        const float (*Ac)[68] = As[p];
        const float (*Bc)[68] = Bs[p];
#pragma unroll
        for (int kk = 0; kk < 16; kk++) {
            float4 a4 = *(const float4*)&Ac[kk][ty * 4];
            float4 b4 = *(const float4*)&Bc[kk][tx * 4];
            acc[0][0] += a4.x * b4.x; acc[0][1] += a4.x * b4.y; acc[0][2] += a4.x * b4.z; acc[0][3] += a4.x * b4.w;
            acc[1][0] += a4.y * b4.x; acc[1][1] += a4.y * b4.y; acc[1][2] += a4.y * b4.z; acc[1][3] += a4.y * b4.w;
            acc[2][0] += a4.z * b4.x; acc[2][1] += a4.z * b4.y; acc[2][2] += a4.z * b4.z; acc[2][3] += a4.z * b4.w;
            acc[3][0] += a4.w * b4.x; acc[3][1] += a4.w * b4.y; acc[3][2] += a4.w * b4.z; acc[3][3] += a4.w * b4.w;
        }
    }

#pragma unroll
    for (int i = 0; i < 4; i++) {
        int row = bm + ty * 4 + i;
#pragma unroll
        for (int j = 0; j < 4; j++) {
            int col = bn + tx * 4 + j;
            float v = acc[i][j];
            if (bias) v += bias[col];
            C[row * N + col] = v;
        }
    }
}

// ---------------- cluster LSTM: one 8-CTA cluster per direction ----------------
// grid = 16 CTAs (2 clusters). 256 threads/CTA. U held in registers.
// Warp owns 4 units (usub = lane>>3); sl = lane&7 is both k-slice and push
// target rank. Butterfly reduce (width 8) leaves gate sums in all 8 lanes;
// all lanes run MUFU-tanh activations redundantly (bit-identical) and carry c.
// Each lane pushes its unit's h to exactly ONE CTA (rank sl): one st.async per
// thread = 32 messages/warp, no sequential push loop. No in-loop __syncthreads
// (R11-proven safe: tid0's re-arm precedes its own push in program order).
__global__ void __launch_bounds__(256, 1) __cluster_dims__(CLU, 1, 1)
lstm_cluster_kernel(int layer) {
    const int dir = blockIdx.x / CLU;     // 0 = forward, 1 = backward
    uint32_t rank;
    asm("mov.u32 %0, %%cluster_ctarank;" : "=r"(rank));

    const float* xw = (dir == 0) ? g_xw_a : g_xw_b;
    const float* Ut = g_Ut[layer * 2 + dir];
    float* out = (layer == 0) ? g_v : g_hcat;
    const int coloff = dir * LL;          // concat column offset

    const int tid  = threadIdx.x;
    const int warp = tid >> 5, lane = tid & 31;
    const int usub = lane >> 3, sl = lane & 7;  // unit-in-warp, k-slice / target rank
    const int u = rank * 32 + warp * 4 + usub;  // hidden unit owned

    __shared__ __align__(16) float h_s[2][LL];
    __shared__ __align__(8) unsigned long long mbar[2];

    // Load this thread's U slice into registers: 4 gates x 8 float4 = 128 regs
    float4 Ug[4][8];
#pragma unroll
    for (int g = 0; g < 4; g++)
#pragma unroll
        for (int j = 0; j < 8; j++)
            Ug[g][j] = *(const float4*)&Ut[(g * LL + u) * LL + j * 32 + sl * 4];

    const uint32_t bar0 = smem_u32(&mbar[0]);
    const uint32_t bar1 = smem_u32(&mbar[1]);

    // init: zero h buffer 0, init barriers, post initial expects
    h_s[0][tid] = 0.f;
    if (tid == 0) {
        asm volatile("mbarrier.init.shared.b64 [%0], 1;" :: "r"(bar0) : "memory");
        asm volatile("mbarrier.init.shared.b64 [%0], 1;" :: "r"(bar1) : "memory");
        asm volatile("mbarrier.arrive.expect_tx.shared.b64 _, [%0], %1;" :: "r"(bar1), "r"(LL * 4) : "memory");
        asm volatile("mbarrier.arrive.expect_tx.shared.b64 _, [%0], %1;" :: "r"(bar0), "r"(LL * 4) : "memory");
    }
    __syncthreads();
    // barriers + zeroed h must be visible cluster-wide before any st.async lands
    asm volatile("barrier.cluster.arrive.aligned;" ::: "memory");
    asm volatile("barrier.cluster.wait.aligned;" ::: "memory");

    // per-lane DSMEM target: this lane pushes unit u's h to CTA rank sl.
    const uint32_t h0u = smem_u32(&h_s[0][u]);
    uint32_t dHme;
    asm("mapa.shared::cluster.u32 %0, %1, %2;" : "=r"(dHme) : "r"(h0u), "r"(sl));
    const uint32_t offB0 = bar0 - h0u;          // delta to mbar[0]
    const uint32_t offB1 = bar1 - h0u;          // delta to mbar[1]
    const uint32_t offH1 = (uint32_t)(LL * 4);  // delta h_s[1] - h_s[0]

    float c = 0.f;                              // carried redundantly in all 8 lanes
    uint32_t ph0 = 0, ph1 = 0;                  // phase parity per barrier

    // prefetch xw for the first token (group-uniform addresses -> broadcast)
    const int tok0 = (dir == 0) ? 0 : (TT - 1);
    float xwv0, xwv1, xwv2, xwv3;
    {
        const float* xp = &xw[tok0 * ZDIM + u];
        xwv0 = __ldg(xp + 0 * LL);
        xwv1 = __ldg(xp + 1 * LL);
        xwv2 = __ldg(xp + 2 * LL);
        xwv3 = __ldg(xp + 3 * LL);
    }

    for (int s = 0; s < TT; s++) {
        if (s > 0) {
            const uint32_t b = (s & 1) ? bar1 : bar0;
            uint32_t& ph = (s & 1) ? ph1 : ph0;
            mbar_wait_parity(b, ph);
            ph ^= 1;
            // re-arm for this barrier's next use (step s+2); tid0's own push
            // below gates all remote tx into b (program order) — no BAR needed.
            if (tid == 0)
                asm volatile("mbarrier.arrive.expect_tx.shared.b64 _, [%0], %1;" :: "r"(b), "r"(LL * 4) : "memory");
        }

        const float* hc = h_s[s & 1];
        const int tok = (dir == 0) ? s : (TT - 1 - s);

        float acc0 = 0.f, acc1 = 0.f, acc2 = 0.f, acc3 = 0.f;
#pragma unroll
        for (int j = 0; j < 8; j++) {
            float4 h4 = *(const float4*)&hc[j * 32 + sl * 4];
            float4 a;
            a = Ug[0][j]; acc0 += a.x * h4.x + a.y * h4.y + a.z * h4.z + a.w * h4.w;
            a = Ug[1][j]; acc1 += a.x * h4.x + a.y * h4.y + a.z * h4.z + a.w * h4.w;
            a = Ug[2][j]; acc2 += a.x * h4.x + a.y * h4.y + a.z * h4.z + a.w * h4.w;
            a = Ug[3][j]; acc3 += a.x * h4.x + a.y * h4.y + a.z * h4.z + a.w * h4.w;
        }
        // butterfly reduce across the 8 slices: result in ALL 8 lanes
#pragma unroll
        for (int off = 4; off; off >>= 1) {
            acc0 += __shfl_xor_sync(0xffffffffu, acc0, off, 8);
            acc1 += __shfl_xor_sync(0xffffffffu, acc1, off, 8);
            acc2 += __shfl_xor_sync(0xffffffffu, acc2, off, 8);
            acc3 += __shfl_xor_sync(0xffffffffu, acc3, off, 8);
        }

        // all lanes compute gates redundantly (bit-identical); MUFU tanh path
        float iv = fsig_hw(acc0 + xwv0);
        float fv = fsig_hw(acc1 + xwv1);
        float gv = ftanh_hw(acc2 + xwv2);
        float ov = fsig_hw(acc3 + xwv3);
        c = fv * c + iv * gv;
        float hv = ov * ftanh_hw(c);

        if (s + 1 < TT) {
            // lane-parallel broadcast: ONE st.async per thread (unit u -> CTA sl)
            const uint32_t q = (s + 1) & 1;
            const uint32_t offH = q ? offH1 : 0u;
            const uint32_t offB = q ? offB1 : offB0;
            asm volatile(
                "st.async.shared::cluster.mbarrier::complete_tx::bytes.b32 [%0], %1, [%2];"
                :: "r"(dHme + offH), "r"(__float_as_uint(hv)), "r"(dHme + offB) : "memory");
        }

        if (sl == 0)
            out[tok * (2 * LL) + coloff + u] = hv;

        if (s + 1 < TT) {
            // prefetch next token's xw while the cluster syncs
            const int ntok = (dir == 0) ? (s + 1) : (TT - 2 - s);
            const float* xp = &xw[ntok * ZDIM + u];
            xwv0 = __ldg(xp + 0 * LL);
            xwv1 = __ldg(xp + 1 * LL);
            xwv2 = __ldg(xp + 2 * LL);
            xwv3 = __ldg(xp + 3 * LL);
        }
    }

    // hygiene: no CTA exits while peers could still address its SMEM
    asm volatile("barrier.cluster.arrive.aligned;" ::: "memory");
    asm volatile("barrier.cluster.wait.aligned;" ::: "memory");
}

// ---------------- pairwise head: out[i,j] = sum_h w[h]*tanh(hf[i,h]+mf[j,h]) + ob ----------------
__global__ void __launch_bounds__(256) pairwise_kernel(
    const float* __restrict__ headf, const float* __restrict__ modf,
    const float* __restrict__ outW, const float* __restrict__ outB,
    float* __restrict__ out) {
    __shared__ __align__(16) float SH[32][132];
    __shared__ float SMt[128][33];
    __shared__ __align__(16) float Wsh[128];

    const int t = threadIdx.x;
    const int i0 = blockIdx.y * 32, j0 = blockIdx.x * 32;
    const int li = t >> 3;
    const int lj = (t & 7) * 4;

    float acc0 = 0.f, acc1 = 0.f, acc2 = 0.f, acc3 = 0.f;

    for (int hc = 0; hc < HH; hc += 128) {
#pragma unroll
        for (int r = 0; r < 4; r++) {
            int idx = t + r * 256;
            int row = idx >> 5;
            int c4 = (idx & 31) * 4;
            float4 hvv = *(const float4*)&headf[(i0 + row) * HH + hc + c4];
            *(float4*)&SH[row][c4] = hvv;
            float4 mvv = *(const float4*)&modf[(j0 + row) * HH + hc + c4];
            SMt[c4 + 0][row] = mvv.x; SMt[c4 + 1][row] = mvv.y;
            SMt[c4 + 2][row] = mvv.z; SMt[c4 + 3][row] = mvv.w;
        }
        if (t < 32) *(float4*)&Wsh[t * 4] = *(const float4*)&outW[hc + t * 4];
        __syncthreads();

#pragma unroll 4
        for (int h = 0; h < 128; h++) {
            float hv = SH[li][h];
            float w = Wsh[h];
            acc0 += w * ftanh_hw(hv + SMt[h][lj + 0]);
            acc1 += w * ftanh_hw(hv + SMt[h][lj + 1]);
            acc2 += w * ftanh_hw(hv + SMt[h][lj + 2]);
            acc3 += w * ftanh_hw(hv + SMt[h][lj + 3]);
        }
        __syncthreads();
    }

    const float ob = outB[0];
    float* orow = &out[(i0 + li) * TT + j0 + lj];
    orow[0] = acc0 + ob;
    orow[1] = acc1 + ob;
    orow[2] = acc2 + ob;
    orow[3] = acc3 + ob;
}

// ---------------- host side ----------------
extern "C" void kernel_launch(void* const* d_in, const int* in_sizes, int n_in,
                              void* d_out, int out_size) {
    (void)in_sizes; (void)n_in; (void)out_size;
    const float* emb     = (const float*)d_in[0];
    const float* W_f1    = (const float*)d_in[1];
    const float* U_f1    = (const float*)d_in[2];
    const float* b_f1    = (const float*)d_in[3];
    const float* W_b1    = (const float*)d_in[4];
    const float* U_b1    = (const float*)d_in[5];
    const float* b_b1    = (const float*)d_in[6];
    const float* W_f2    = (const float*)d_in[7];
    const float* U_f2    = (const float*)d_in[8];
    const float* b_f2    = (const float*)d_in[9];
    const float* W_b2    = (const float*)d_in[10];
    const float* U_b2    = (const float*)d_in[11];
    const float* b_b2    = (const float*)d_in[12];
    const float* FOH     = (const float*)d_in[13];
    const float* FOM     = (const float*)d_in[14];
    const float* hidBias = (const float*)d_in[15];
    const float* outW    = (const float*)d_in[16];
    const float* outBias = (const float*)d_in[17];

    float *xwa, *xwb, *v, *hcat, *headf, *modf;
    cudaGetSymbolAddress((void**)&xwa,   g_xw_a);
    cudaGetSymbolAddress((void**)&xwb,   g_xw_b);
    cudaGetSymbolAddress((void**)&v,     g_v);
    cudaGetSymbolAddress((void**)&hcat,  g_hcat);
    cudaGetSymbolAddress((void**)&headf, g_headf);
    cudaGetSymbolAddress((void**)&modf,  g_modf);

    // 1. transpose all recurrent matrices
    transposeU_kernel<<<dim3(ZDIM / 32, LL / 32, 4), dim3(32, 8)>>>(U_f1, U_b1, U_f2, U_b2);

    // 2. layer-1 input projections (both directions, bias folded in)
    gemm2_kernel<<<dim3(ZDIM / 64, TT / 64, 2), 256>>>(
        emb, emb, W_f1, W_b1, b_f1, b_b1, xwa, xwb, TT, ZDIM, DD);

    // 3. layer-1 BiLSTM (fw + bw clusters concurrently), writes concat layout -> v
    lstm_cluster_kernel<<<2 * CLU, 256>>>(0);

    // 4. layer-2 input projections
    gemm2_kernel<<<dim3(ZDIM / 64, TT / 64, 2), 256>>>(
        v, v, W_f2, W_b2, b_f2, b_b2, xwa, xwb, TT, ZDIM, 2 * LL);

    // 5. layer-2 BiLSTM -> hcat
    lstm_cluster_kernel<<<2 * CLU, 256>>>(1);

    // 6. head projections (hidBias folded into headfov)
    gemm2_kernel<<<dim3(HH / 64, TT / 64, 2), 256>>>(
        hcat, hcat, FOH, FOM, hidBias, nullptr, headf, modf, TT, HH, 2 * LL);

    // 7. pairwise scores
    pairwise_kernel<<<dim3(TT / 32, TT / 32), 256>>>(headf, modf, outW, outBias, (float*)d_out);
}

// round 14
// speedup vs baseline: 1.3473x; 1.0758x over previous
#include <cuda_runtime.h>
#include <cuda_fp16.h>
#include <cstdint>

#define TT 512
#define DD 256
#define LL 256
#define HH 512
#define ZDIM 1024
#define CLU 8    // CTAs per cluster = per LSTM direction

// ---------------- device scratch (no allocations allowed) ----------------
__device__ __align__(16) float g_xw_a[TT * ZDIM];
__device__ __align__(16) float g_xw_b[TT * ZDIM];
__device__ __align__(16) __half g_Ut_h[4][ZDIM * LL];  // transposed U, fp16: [col][k]
__device__ __align__(16) float g_v[TT * 2 * LL];
__device__ __align__(16) float g_hcat[TT * 2 * LL];
__device__ __align__(16) float g_headf[TT * HH];
__device__ __align__(16) float g_modf[TT * HH];

// ---------------- fast activations ----------------
__device__ __forceinline__ float ftanh_hw(float x) { // MUFU tanh
    float r;
    asm("tanh.approx.f32 %0, %1;" : "=f"(r) : "f"(x));
    return r;
}
__device__ __forceinline__ float fsig_hw(float x) {  // sigmoid via MUFU tanh
    return fmaf(ftanh_hw(0.5f * x), 0.5f, 0.5f);
}

__device__ __forceinline__ uint32_t smem_u32(const void* p) {
    uint32_t a;
    asm("{ .reg .u64 t; cvta.to.shared.u64 t, %1; cvt.u32.u64 %0, t; }" : "=r"(a) : "l"(p));
    return a;
}

__device__ __forceinline__ __half2 shfl_xor_h2(__half2 v, int off, int width) {
    uint32_t b = *reinterpret_cast<uint32_t*>(&v);
    b = __shfl_xor_sync(0xffffffffu, b, off, width);
    return *reinterpret_cast<__half2*>(&b);
}

// try_wait parity with sleep (acquire)
__device__ __forceinline__ void mbar_wait_parity(uint32_t mbar, uint32_t parity) {
    uint32_t done;
    asm volatile(
        "{\n\t"
        ".reg .pred p;\n\t"
        "mbarrier.try_wait.parity.acquire.cta.shared::cta.b64 p, [%1], %2;\n\t"
        "selp.b32 %0, 1, 0, p;\n\t"
        "}"
        : "=r"(done) : "r"(mbar), "r"(parity) : "memory");
    if (!done) {
        asm volatile(
            "{\n\t"
            ".reg .pred P1;\n\t"
            "WAIT_LOOP_%=:\n\t"
            "mbarrier.try_wait.parity.acquire.cta.shared::cta.b64 P1, [%0], %1, 0x989680;\n\t"
            "@P1 bra.uni WAIT_DONE_%=;\n\t"
            "bra.uni WAIT_LOOP_%=;\n\t"
            "WAIT_DONE_%=:\n\t"
            "}"
            :: "r"(mbar), "r"(parity) : "memory");
    }
}

// ---------------- U transpose: [256,1024] -> [1024,256] fp16, x4 ----------------
__global__ void transposeU_kernel(const float* __restrict__ u0, const float* __restrict__ u1,
                                  const float* __restrict__ u2, const float* __restrict__ u3) {
    __shared__ float tile[32][33];
    const float* src = (blockIdx.z == 0) ? u0 : (blockIdx.z == 1) ? u1 : (blockIdx.z == 2) ? u2 : u3;
    __half* dst = g_Ut_h[blockIdx.z];
    int j  = blockIdx.x * 32 + threadIdx.x;   // column in U (0..1023)
    int k0 = blockIdx.y * 32;                 // row chunk (0..255)
#pragma unroll
    for (int r = 0; r < 32; r += 8)
        tile[threadIdx.y + r][threadIdx.x] = src[(k0 + threadIdx.y + r) * ZDIM + j];
    __syncthreads();
    int k  = k0 + threadIdx.x;
    int jo = blockIdx.x * 32;
#pragma unroll
    for (int r = 0; r < 32; r += 8)
        dst[(jo + threadIdx.y + r) * LL + k] = __float2half(tile[threadIdx.x][threadIdx.y + r]);
}

// ---------------- dual fp32 tiled GEMM, double-buffered smem ----------------
__global__ void __launch_bounds__(256) gemm2_kernel(
    const float* __restrict__ A0, const float* __restrict__ A1,
    const float* __restrict__ B0, const float* __restrict__ B1,
    const float* __restrict__ bias0, const float* __restrict__ bias1,
    float* __restrict__ C0, float* __restrict__ C1,
    int M, int N, int K) {
    const float* A    = (blockIdx.z == 0) ? A0 : A1;
    const float* B    = (blockIdx.z == 0) ? B0 : B1;
    const float* bias = (blockIdx.z == 0) ? bias0 : bias1;
    float* C          = (blockIdx.z == 0) ? C0 : C1;

    __shared__ __align__(16) float As[2][16][68];
    __shared__ __align__(16) float Bs[2][16][68];
    const int tid = threadIdx.x;
    const int tx = tid & 15, ty = tid >> 4;
    const int bm = blockIdx.y * 64, bn = blockIdx.x * 64;

    const int ar = tid >> 2;
    const int ac = (tid & 3) * 4;
    const int br = tid >> 4;
    const int bc = (tid & 15) * 4;

    float acc[4][4];
#pragma unroll
    for (int i = 0; i < 4; i++)
#pragma unroll
        for (int j = 0; j < 4; j++) acc[i][j] = 0.f;

    {
        float4 av = *(const float4*)&A[(bm + ar) * K + ac];
        As[0][ac + 0][ar] = av.x; As[0][ac + 1][ar] = av.y;
        As[0][ac + 2][ar] = av.z; As[0][ac + 3][ar] = av.w;
        float4 bv = *(const float4*)&B[br * N + bn + bc];
        *(float4*)&Bs[0][br][bc] = bv;
    }
    __syncthreads();

    int p = 0;
    for (int k0 = 16; k0 < K; k0 += 16) {
        float4 av = *(const float4*)&A[(bm + ar) * K + k0 + ac];
        float4 bv = *(const float4*)&B[(k0 + br) * N + bn + bc];

        {
            const float (*Ac)[68] = As[p];
            const float (*Bc)[68] = Bs[p];
#pragma unroll
            for (int kk = 0; kk < 16; kk++) {
                float4 a4 = *(const float4*)&Ac[kk][ty * 4];
                float4 b4 = *(const float4*)&Bc[kk][tx * 4];
                acc[0][0] += a4.x * b4.x; acc[0][1] += a4.x * b4.y; acc[0][2] += a4.x * b4.z; acc[0][3] += a4.x * b4.w;
                acc[1][0] += a4.y * b4.x; acc[1][1] += a4.y * b4.y; acc[1][2] += a4.y * b4.z; acc[1][3] += a4.y * b4.w;
                acc[2][0] += a4.z * b4.x; acc[2][1] += a4.z * b4.y; acc[2][2] += a4.z * b4.z; acc[2][3] += a4.z * b4.w;
                acc[3][0] += a4.w * b4.x; acc[3][1] += a4.w * b4.y; acc[3][2] += a4.w * b4.z; acc[3][3] += a4.w * b4.w;
            }
        }

        p ^= 1;
        As[p][ac + 0][ar] = av.x; As[p][ac + 1][ar] = av.y;
        As[p][ac + 2][ar] = av.z; As[p][ac + 3][ar] = av.w;
        *(float4*)&Bs[p][br][bc] = bv;
        __syncthreads();
    }

    {
        const float (*Ac)[68] = As[p];
        const float (*Bc)[68] = Bs[p];
#pragma unroll
        for (int kk = 0; kk < 16; kk++) {
            float4 a4 = *(const float4*)&Ac[kk][ty * 4];
            float4 b4 = *(const float4*)&Bc[kk][tx * 4];
            acc[0][0] += a4.x * b4.x; acc[0][1] += a4.x * b4.y; acc[0][2] += a4.x * b4.z; acc[0][3] += a4.x * b4.w;
            acc[1][0] += a4.y * b4.x; acc[1][1] += a4.y * b4.y; acc[1][2] += a4.y * b4.z; acc[1][3] += a4.y * b4.w;
            acc[2][0] += a4.z * b4.x; acc[2][1] += a4.z * b4.y; acc[2][2] += a4.z * b4.z; acc[2][3] += a4.z * b4.w;
            acc[3][0] += a4.w * b4.x; acc[3][1] += a4.w * b4.y; acc[3][2] += a4.w * b4.z; acc[3][3] += a4.w * b4.w;
        }
    }

#pragma unroll
    for (int i = 0; i < 4; i++) {
        int row = bm + ty * 4 + i;
#pragma unroll
        for (int j = 0; j < 4; j++) {
            int col = bn + tx * 4 + j;
            float v = acc[i][j];
            if (bias) v += bias[col];
            C[row * N + col] = v;
        }
    }
}

// ---------------- cluster LSTM: one 8-CTA cluster per direction, fp16 U·h ----------------
// grid = 16 CTAs (2 clusters). 256 threads/CTA. U in fp16 registers (half2).
// Lane sl covers k in {j*64+sl*8 .. +7}, j=0..3 (32 k). h kept in smem as fp16:
// 4 conflict-free LDS.128 per lane. Inner product = 64 HFMA2/thread (256-cyc
// SMSP floor vs 512 fp32). Butterfly reduce on half2 (3 shfl + 3 HADD2/gate),
// xw added in fp32; c and out[] stay fp32. h pushed as fp16 pairs: even-usub
// lanes pack (u, u+1) via one shfl and push ONE b32 to CTA rank sl.
// No in-loop __syncthreads (R11-proven).
__global__ void __launch_bounds__(256, 1) __cluster_dims__(CLU, 1, 1)
lstm_cluster_kernel(int layer) {
    const int dir = blockIdx.x / CLU;     // 0 = forward, 1 = backward
    uint32_t rank;
    asm("mov.u32 %0, %%cluster_ctarank;" : "=r"(rank));

    const float* xw = (dir == 0) ? g_xw_a : g_xw_b;
    const __half* Ut = g_Ut_h[layer * 2 + dir];
    float* out = (layer == 0) ? g_v : g_hcat;
    const int coloff = dir * LL;

    const int tid  = threadIdx.x;
    const int warp = tid >> 5, lane = tid & 31;
    const int usub = lane >> 3, sl = lane & 7;  // unit-in-warp, k-slice / target rank
    const int u = rank * 32 + warp * 4 + usub;  // hidden unit owned

    __shared__ __align__(16) __half h_s[2][LL];     // fp16 h, 512 B per buffer
    __shared__ __align__(8) unsigned long long mbar[2];

    // U slice in fp16 registers: 4 gates x 4 j x 4 half2 = 64 regs
    __half2 Ug[4][4][4];
#pragma unroll
    for (int g = 0; g < 4; g++)
#pragma unroll
        for (int j = 0; j < 4; j++) {
            uint4 w = *(const uint4*)&Ut[(size_t)(g * LL + u) * LL + j * 64 + sl * 8];
            Ug[g][j][0] = *reinterpret_cast<__half2*>(&w.x);
            Ug[g][j][1] = *reinterpret_cast<__half2*>(&w.y);
            Ug[g][j][2] = *reinterpret_cast<__half2*>(&w.z);
            Ug[g][j][3] = *reinterpret_cast<__half2*>(&w.w);
        }

    const uint32_t bar0 = smem_u32(&mbar[0]);
    const uint32_t bar1 = smem_u32(&mbar[1]);

    // init: zero h buffer 0 (fp16), init barriers, post initial expects (512 B)
    h_s[0][tid] = __float2half(0.f);
    if (tid == 0) {
        asm volatile("mbarrier.init.shared.b64 [%0], 1;" :: "r"(bar0) : "memory");
        asm volatile("mbarrier.init.shared.b64 [%0], 1;" :: "r"(bar1) : "memory");
        asm volatile("mbarrier.arrive.expect_tx.shared.b64 _, [%0], %1;" :: "r"(bar1), "r"(LL * 2) : "memory");
        asm volatile("mbarrier.arrive.expect_tx.shared.b64 _, [%0], %1;" :: "r"(bar0), "r"(LL * 2) : "memory");
    }
    __syncthreads();
    asm volatile("barrier.cluster.arrive.aligned;" ::: "memory");
    asm volatile("barrier.cluster.wait.aligned;" ::: "memory");

    // per-lane DSMEM target: even-usub lanes push pair (u, u+1) as b32 to rank sl
    const uint32_t hpair = smem_u32(&h_s[0][u & ~1]);   // 4B-aligned (u even)
    uint32_t dHme;
    asm("mapa.shared::cluster.u32 %0, %1, %2;" : "=r"(dHme) : "r"(hpair), "r"(sl));
    const uint32_t offB0 = bar0 - hpair;
    const uint32_t offB1 = bar1 - hpair;
    const uint32_t offH1 = (uint32_t)(LL * 2);          // fp16 buffer stride
    const bool pusher = ((usub & 1) == 0);

    float c = 0.f;                                      // redundant in all 8 lanes
    uint32_t ph0 = 0, ph1 = 0;

    const int tok0 = (dir == 0) ? 0 : (TT - 1);
    float xwv0, xwv1, xwv2, xwv3;
    {
        const float* xp = &xw[tok0 * ZDIM + u];
        xwv0 = __ldg(xp + 0 * LL);
        xwv1 = __ldg(xp + 1 * LL);
        xwv2 = __ldg(xp + 2 * LL);
        xwv3 = __ldg(xp + 3 * LL);
    }

    for (int s = 0; s < TT; s++) {
        if (s > 0) {
            const uint32_t b = (s & 1) ? bar1 : bar0;
            uint32_t& ph = (s & 1) ? ph1 : ph0;
            mbar_wait_parity(b, ph);
            ph ^= 1;
            if (tid == 0)
                asm volatile("mbarrier.arrive.expect_tx.shared.b64 _, [%0], %1;" :: "r"(b), "r"(LL * 2) : "memory");
        }

        const __half* hc = h_s[s & 1];
        const int tok = (dir == 0) ? s : (TT - 1 - s);

        // load h slice: 4 x LDS.128, conflict-free (chunk = (sl + 4j) mod 8)
        __half2 h2[4][4];
#pragma unroll
        for (int j = 0; j < 4; j++) {
            uint4 w = *(const uint4*)&hc[j * 64 + sl * 8];
            h2[j][0] = *reinterpret_cast<__half2*>(&w.x);
            h2[j][1] = *reinterpret_cast<__half2*>(&w.y);
            h2[j][2] = *reinterpret_cast<__half2*>(&w.z);
            h2[j][3] = *reinterpret_cast<__half2*>(&w.w);
        }

        __half2 a0 = __float2half2_rn(0.f), a1 = a0, a2 = a0, a3 = a0;
#pragma unroll
        for (int j = 0; j < 4; j++)
#pragma unroll
            for (int p = 0; p < 4; p++) {
                a0 = __hfma2(Ug[0][j][p], h2[j][p], a0);
                a1 = __hfma2(Ug[1][j][p], h2[j][p], a1);
                a2 = __hfma2(Ug[2][j][p], h2[j][p], a2);
                a3 = __hfma2(Ug[3][j][p], h2[j][p], a3);
            }
        // butterfly reduce across the 8 slices (packed half2): result in all lanes
#pragma unroll
        for (int off = 4; off; off >>= 1) {
            a0 = __hadd2(a0, shfl_xor_h2(a0, off, 8));
            a1 = __hadd2(a1, shfl_xor_h2(a1, off, 8));
            a2 = __hadd2(a2, shfl_xor_h2(a2, off, 8));
            a3 = __hadd2(a3, shfl_xor_h2(a3, off, 8));
        }
        float acc0 = __low2float(a0) + __high2float(a0);
        float acc1 = __low2float(a1) + __high2float(a1);
        float acc2 = __low2float(a2) + __high2float(a2);
        float acc3 = __low2float(a3) + __high2float(a3);

        // all lanes compute gates redundantly (bit-identical); MUFU tanh path
        float iv = fsig_hw(acc0 + xwv0);
        float fv = fsig_hw(acc1 + xwv1);
        float gv = ftanh_hw(acc2 + xwv2);
        float ov = fsig_hw(acc3 + xwv3);
        c = fv * c + iv * gv;
        float hv = ov * ftanh_hw(c);

        if (s + 1 < TT) {
            // pack fp16 pair (u even: low = mine, high = partner's at lane+8)
            uint32_t mine = (uint32_t)__half_as_ushort(__float2half(hv));
            uint32_t other = __shfl_xor_sync(0xffffffffu, mine, 8);
            if (pusher) {
                uint32_t pkt = mine | (other << 16);
                const uint32_t q = (s + 1) & 1;
                const uint32_t offH = q ? offH1 : 0u;
                const uint32_t offB = q ? offB1 : offB0;
                asm volatile(
                    "st.async.shared::cluster.mbarrier::complete_tx::bytes.b32 [%0], %1, [%2];"
                    :: "r"(dHme + offH), "r"(pkt), "r"(dHme + offB) : "memory");
            }
        }

        if (sl == 0)
            out[tok * (2 * LL) + coloff + u] = hv;   // fp32 output

        if (s + 1 < TT) {
            const int ntok = (dir == 0) ? (s + 1) : (TT - 2 - s);
            const float* xp = &xw[ntok * ZDIM + u];
            xwv0 = __ldg(xp + 0 * LL);
            xwv1 = __ldg(xp + 1 * LL);
            xwv2 = __ldg(xp + 2 * LL);
            xwv3 = __ldg(xp + 3 * LL);
        }
    }

    asm volatile("barrier.cluster.arrive.aligned;" ::: "memory");
    asm volatile("barrier.cluster.wait.aligned;" ::: "memory");
}

// ---------------- pairwise head: out[i,j] = sum_h w[h]*tanh(hf[i,h]+mf[j,h]) + ob ----------------
__global__ void __launch_bounds__(256) pairwise_kernel(
    const float* __restrict__ headf, const float* __restrict__ modf,
    const float* __restrict__ outW, const float* __restrict__ outB,
    float* __restrict__ out) {
    __shared__ __align__(16) float SH[32][132];
    __shared__ float SMt[128][33];
    __shared__ __align__(16) float Wsh[128];

    const int t = threadIdx.x;
    const int i0 = blockIdx.y * 32, j0 = blockIdx.x * 32;
    const int li = t >> 3;
    const int lj = (t & 7) * 4;

    float acc0 = 0.f, acc1 = 0.f, acc2 = 0.f, acc3 = 0.f;

    for (int hc = 0; hc < HH; hc += 128) {
#pragma unroll
        for (int r = 0; r < 4; r++) {
            int idx = t + r * 256;
            int row = idx >> 5;
            int c4 = (idx & 31) * 4;
            float4 hvv = *(const float4*)&headf[(i0 + row) * HH + hc + c4];
            *(float4*)&SH[row][c4] = hvv;
            float4 mvv = *(const float4*)&modf[(j0 + row) * HH + hc + c4];
            SMt[c4 + 0][row] = mvv.x; SMt[c4 + 1][row] = mvv.y;
            SMt[c4 + 2][row] = mvv.z; SMt[c4 + 3][row] = mvv.w;
        }
        if (t < 32) *(float4*)&Wsh[t * 4] = *(const float4*)&outW[hc + t * 4];
        __syncthreads();

#pragma unroll 4
        for (int h = 0; h < 128; h++) {
            float hv = SH[li][h];
            float w = Wsh[h];
            acc0 += w * ftanh_hw(hv + SMt[h][lj + 0]);
            acc1 += w * ftanh_hw(hv + SMt[h][lj + 1]);
            acc2 += w * ftanh_hw(hv + SMt[h][lj + 2]);
            acc3 += w * ftanh_hw(hv + SMt[h][lj + 3]);
        }
        __syncthreads();
    }

    const float ob = outB[0];
    float* orow = &out[(i0 + li) * TT + j0 + lj];
    orow[0] = acc0 + ob;
    orow[1] = acc1 + ob;
    orow[2] = acc2 + ob;
    orow[3] = acc3 + ob;
}

// ---------------- host side ----------------
extern "C" void kernel_launch(void* const* d_in, const int* in_sizes, int n_in,
                              void* d_out, int out_size) {
    (void)in_sizes; (void)n_in; (void)out_size;
    const float* emb     = (const float*)d_in[0];
    const float* W_f1    = (const float*)d_in[1];
    const float* U_f1    = (const float*)d_in[2];
    const float* b_f1    = (const float*)d_in[3];
    const float* W_b1    = (const float*)d_in[4];
    const float* U_b1    = (const float*)d_in[5];
    const float* b_b1    = (const float*)d_in[6];
    const float* W_f2    = (const float*)d_in[7];
    const float* U_f2    = (const float*)d_in[8];
    const float* b_f2    = (const float*)d_in[9];
    const float* W_b2    = (const float*)d_in[10];
    const float* U_b2    = (const float*)d_in[11];
    const float* b_b2    = (const float*)d_in[12];
    const float* FOH     = (const float*)d_in[13];
    const float* FOM     = (const float*)d_in[14];
    const float* hidBias = (const float*)d_in[15];
    const float* outW    = (const float*)d_in[16];
    const float* outBias = (const float*)d_in[17];

    float *xwa, *xwb, *v, *hcat, *headf, *modf;
    cudaGetSymbolAddress((void**)&xwa,   g_xw_a);
    cudaGetSymbolAddress((void**)&xwb,   g_xw_b);
    cudaGetSymbolAddress((void**)&v,     g_v);
    cudaGetSymbolAddress((void**)&hcat,  g_hcat);
    cudaGetSymbolAddress((void**)&headf, g_headf);
    cudaGetSymbolAddress((void**)&modf,  g_modf);

    // 1. transpose + fp16-convert all recurrent matrices
    transposeU_kernel<<<dim3(ZDIM / 32, LL / 32, 4), dim3(32, 8)>>>(U_f1, U_b1, U_f2, U_b2);

    // 2. layer-1 input projections (both directions, bias folded in)
    gemm2_kernel<<<dim3(ZDIM / 64, TT / 64, 2), 256>>>(
        emb, emb, W_f1, W_b1, b_f1, b_b1, xwa, xwb, TT, ZDIM, DD);

    // 3. layer-1 BiLSTM (fw + bw clusters concurrently), writes concat layout -> v
    lstm_cluster_kernel<<<2 * CLU, 256>>>(0);

    // 4. layer-2 input projections
    gemm2_kernel<<<dim3(ZDIM / 64, TT / 64, 2), 256>>>(
        v, v, W_f2, W_b2, b_f2, b_b2, xwa, xwb, TT, ZDIM, 2 * LL);

    // 5. layer-2 BiLSTM -> hcat
    lstm_cluster_kernel<<<2 * CLU, 256>>>(1);

    // 6. head projections (hidBias folded into headfov)
    gemm2_kernel<<<dim3(HH / 64, TT / 64, 2), 256>>>(
        hcat, hcat, FOH, FOM, hidBias, nullptr, headf, modf, TT, HH, 2 * LL);

    // 7. pairwise scores
    pairwise_kernel<<<dim3(TT / 32, TT / 32), 256>>>(headf, modf, outW, outBias, (float*)d_out);
}